// round 16
// baseline (speedup 1.0000x reference)
#include <cuda_runtime.h>
#include <cuda_fp16.h>

#define BB 2
#define EE 1024
#define TT 2048
#define HH 16
#define DHH 64
#define SCALE 0.03125f
#define S2LOG2E 0.045084235f   // SCALE * log2(e)

// ---------------------------------------------------------------------------
// fp16 scratch (static device arrays; 16B aligned for cp.async / vector ops)
// ---------------------------------------------------------------------------
__device__ __align__(16) __half g_xh[3*BB*EE*TT];   // converted q,k,v inputs
__device__ __align__(16) __half g_wh[4*EE*EE];      // converted Wq,Wk,Wv,Wo
__device__ __align__(16) __half g_qp[BB*EE*TT];     // Q proj [e][t]
__device__ __align__(16) __half g_kp[BB*EE*TT];     // K proj [e][t]
__device__ __align__(16) __half g_vp[BB*EE*TT];     // V proj [e][t]
__device__ __align__(16) __half g_vs[BB*EE*TT];     // V * rl
__device__ __align__(16) __half g_oh[BB*EE*TT];     // attention output O
__device__ __align__(16) __half g_att[(size_t)BB*HH*TT*TT];  // unnorm exp(s)*km
__device__ __align__(16) __half g_kmh[BB*TT];       // fp16 key mask

// ---------------------------------------------------------------------------
__device__ __forceinline__ unsigned smaddr(const void* p){
    return (unsigned)__cvta_generic_to_shared(p);
}
__device__ __forceinline__ void cpa16(unsigned dst, const void* src){
    asm volatile("cp.async.cg.shared.global [%0], [%1], 16;" :: "r"(dst), "l"(src));
}
__device__ __forceinline__ void cpa_commit(){
    asm volatile("cp.async.commit_group;");
}
template<int N> __device__ __forceinline__ void cpa_wait(){
    asm volatile("cp.async.wait_group %0;" :: "n"(N));
}
__device__ __forceinline__ void ldsm4(unsigned r[4], unsigned addr){
    asm volatile("ldmatrix.sync.aligned.m8n8.x4.shared.b16 {%0,%1,%2,%3}, [%4];"
        : "=r"(r[0]),"=r"(r[1]),"=r"(r[2]),"=r"(r[3]) : "r"(addr));
}
__device__ __forceinline__ void ldsm4t(unsigned r[4], unsigned addr){
    asm volatile("ldmatrix.sync.aligned.m8n8.x4.trans.shared.b16 {%0,%1,%2,%3}, [%4];"
        : "=r"(r[0]),"=r"(r[1]),"=r"(r[2]),"=r"(r[3]) : "r"(addr));
}
__device__ __forceinline__ void mma16(float c[4], const unsigned a[4], const unsigned b[2]){
    asm volatile("mma.sync.aligned.m16n8k16.row.col.f32.f16.f16.f32 "
        "{%0,%1,%2,%3},{%4,%5,%6,%7},{%8,%9},{%0,%1,%2,%3};"
        : "+f"(c[0]),"+f"(c[1]),"+f"(c[2]),"+f"(c[3])
        : "r"(a[0]),"r"(a[1]),"r"(a[2]),"r"(a[3]),"r"(b[0]),"r"(b[1]));
}
__device__ __forceinline__ unsigned h2u(__half2 h){
    return *reinterpret_cast<unsigned*>(&h);
}
__device__ __forceinline__ unsigned ex2h2(unsigned x){
    unsigned r;
    asm("ex2.approx.f16x2 %0, %1;" : "=r"(r) : "r"(x));
    return r;
}
__device__ __forceinline__ unsigned mulh2(unsigned a, unsigned b){
    unsigned r;
    asm("mul.f16x2 %0, %1, %2;" : "=r"(r) : "r"(a), "r"(b));
    return r;
}

// ===========================================================================
// Converters
// ===========================================================================
__global__ void __launch_bounds__(256)
cvt_in(const float* __restrict__ q, const float* __restrict__ k,
       const float* __restrict__ v)
{
    const float* src = (blockIdx.z == 0) ? q : (blockIdx.z == 1) ? k : v;
    __half* dst = g_xh + (size_t)blockIdx.z * BB * EE * TT;
    size_t i = ((size_t)blockIdx.x * 256 + threadIdx.x) * 4;
    float4 x = *(const float4*)&src[i];
    *(__half2*)&dst[i]     = __floats2half2_rn(x.x, x.y);
    *(__half2*)&dst[i + 2] = __floats2half2_rn(x.z, x.w);
}

__global__ void __launch_bounds__(256)
cvt_w(const float* __restrict__ wq, const float* __restrict__ wk,
      const float* __restrict__ wv, const float* __restrict__ wo)
{
    const float* src = (blockIdx.z == 0) ? wq : (blockIdx.z == 1) ? wk :
                       (blockIdx.z == 2) ? wv : wo;
    __half* dst = g_wh + (size_t)blockIdx.z * EE * EE;
    size_t i = ((size_t)blockIdx.x * 256 + threadIdx.x) * 4;
    float4 x = *(const float4*)&src[i];
    *(__half2*)&dst[i]     = __floats2half2_rn(x.x, x.y);
    *(__half2*)&dst[i + 2] = __floats2half2_rn(x.z, x.w);
}

__global__ void __launch_bounds__(256)
cvt_km(const float* __restrict__ km)
{
    int i = blockIdx.x * 256 + threadIdx.x;   // BB*TT = 4096
    g_kmh[i] = __float2half_rn(km[i]);
}

// ===========================================================================
// conv1x1 GEMM (fp16 in, fp32 acc): Y[o,t] = mask[t]*sum_c W[o,c]X[c,t] + b[o]
// 128(o)x128(t) tile, K staged 32, 4-stage cp.async with tail commits.
// Round-14 proven inner loop; __launch_bounds__(256,3): 3 CTA/SM
// (smem 3x75.8=227.3KB fits; regs capped 85, spill to L1 is cheap at 4% DRAM).
// ===========================================================================
#define CV_AP 40
#define CV_BP 136
#define CV_A_H  (128*CV_AP)
#define CV_STG_H (CV_A_H + 32*CV_BP)
#define CV_SMEM (4*CV_STG_H*2)

template<bool OUT_HALF>
__device__ __forceinline__ void gemm_conv(
    const __half* __restrict__ Wh, const __half* __restrict__ Xb,
    const float* __restrict__ bias, const float* __restrict__ maskb,
    void* __restrict__ Yv, size_t y_off)
{
    extern __shared__ __half sh[];
    const int tid = threadIdx.x, lane = tid & 31, warp = tid >> 5;
    const int g = lane >> 2, t4 = lane & 3;
    const int wm = warp >> 1, wn = warp & 1;
    const int l15 = lane & 15, lhi = (lane >> 4) * 8;
    const int o0 = blockIdx.y * 128, t0 = blockIdx.x * 128;

    float acc[2][8][4];
    #pragma unroll
    for (int i = 0; i < 2; i++)
        #pragma unroll
        for (int j = 0; j < 8; j++)
            #pragma unroll
            for (int e = 0; e < 4; e++) acc[i][j][e] = 0.f;

    auto issue = [&](int s) {
        int k0 = s * 32;
        unsigned ab = smaddr(sh + (s & 3) * CV_STG_H);
        unsigned bb = ab + CV_A_H * 2;
        #pragma unroll
        for (int l = 0; l < 2; l++) {
            int idx = tid + l * 256;
            int r = idx >> 2, c8 = (idx & 3) * 8;
            cpa16(ab + (r * CV_AP + c8) * 2, Wh + (size_t)(o0 + r) * EE + k0 + c8);
        }
        #pragma unroll
        for (int l = 0; l < 2; l++) {
            int idx = tid + l * 256;
            int r = idx >> 4, c8 = (idx & 15) * 8;
            cpa16(bb + (r * CV_BP + c8) * 2, Xb + (size_t)(k0 + r) * TT + t0 + c8);
        }
        cpa_commit();
    };

    const int NS = EE / 32;
    issue(0); issue(1); issue(2);

    for (int s = 0; s < NS; s++) {
        cpa_wait<2>();
        __syncthreads();
        unsigned ab = smaddr(sh + (s & 3) * CV_STG_H);
        unsigned bb = ab + CV_A_H * 2;
        #pragma unroll
        for (int kk = 0; kk < 32; kk += 16) {
            unsigned a[2][4], bf[8][2];
            #pragma unroll
            for (int mt = 0; mt < 2; mt++)
                ldsm4(a[mt], ab + ((wm*32 + mt*16 + l15) * CV_AP + kk + lhi) * 2);
            #pragma unroll
            for (int nb = 0; nb < 4; nb++) {
                unsigned r[4];
                ldsm4t(r, bb + ((kk + l15) * CV_BP + wn*64 + nb*16 + lhi) * 2);
                bf[2*nb][0]   = r[0]; bf[2*nb][1]   = r[1];
                bf[2*nb+1][0] = r[2]; bf[2*nb+1][1] = r[3];
            }
            #pragma unroll
            for (int mt = 0; mt < 2; mt++)
                #pragma unroll
                for (int nt = 0; nt < 8; nt++)
                    mma16(acc[mt][nt], a[mt], bf[nt]);
        }
        if (s + 3 < NS) issue(s + 3);
        else            cpa_commit();
    }

    #pragma unroll
    for (int mt = 0; mt < 2; mt++) {
        int o_lo = o0 + wm * 32 + mt * 16 + g;
        float b_lo = bias[o_lo], b_hi = bias[o_lo + 8];
        #pragma unroll
        for (int nt = 0; nt < 8; nt++) {
            int t = t0 + wn * 64 + nt * 8 + 2 * t4;
            float mk0 = maskb[t], mk1 = maskb[t + 1];
            float y00 = mk0 * acc[mt][nt][0] + b_lo;
            float y01 = mk1 * acc[mt][nt][1] + b_lo;
            float y10 = mk0 * acc[mt][nt][2] + b_hi;
            float y11 = mk1 * acc[mt][nt][3] + b_hi;
            if (OUT_HALF) {
                __half* Y = (__half*)Yv + y_off;
                *(__half2*)&Y[(size_t)o_lo * TT + t]       = __floats2half2_rn(y00, y01);
                *(__half2*)&Y[(size_t)(o_lo + 8) * TT + t] = __floats2half2_rn(y10, y11);
            } else {
                float* Y = (float*)Yv + y_off;
                *(float2*)&Y[(size_t)o_lo * TT + t]       = make_float2(y00, y01);
                *(float2*)&Y[(size_t)(o_lo + 8) * TT + t] = make_float2(y10, y11);
            }
        }
    }
}

__global__ void __launch_bounds__(256, 3)
conv3_kernel(const float* __restrict__ qm, const float* __restrict__ km,
             const float* __restrict__ vm,
             const float* __restrict__ bq, const float* __restrict__ bk,
             const float* __restrict__ bv)
{
    int m = blockIdx.z >> 1;
    int b = blockIdx.z & 1;
    const __half* Wh = g_wh + (size_t)m * EE * EE;
    const __half* Xb = g_xh + ((size_t)m * BB + b) * EE * TT;
    size_t yoff = (size_t)b * EE * TT;
    const float* mask = ((m == 0) ? qm : (m == 1) ? km : vm) + (size_t)b * TT;
    const float* bias = (m == 0) ? bq : (m == 1) ? bk : bv;
    __half* Y = (m == 0) ? g_qp : (m == 1) ? g_kp : g_vp;
    gemm_conv<true>(Wh, Xb, bias, mask, Y, yoff);
}

__global__ void __launch_bounds__(256, 3)
conv_final_kernel(const float* __restrict__ bo, const float* __restrict__ km,
                  float* __restrict__ out)
{
    int b = blockIdx.z;
    gemm_conv<false>(g_wh + (size_t)3 * EE * EE,
                     g_oh + (size_t)b * EE * TT,
                     bo, km + (size_t)b * TT, out, (size_t)b * EE * TT);
}

// ===========================================================================
// Scores (round-14 proven, ~108us): per (b,h, 64 q rows).
// P[q,k] = exp(s*qm*km*scale)*km (fp16). Q pre-scaled at staging; fp16 kmask;
// half2 epilogue via ex2.approx.f16x2; l via mma vs ones B-frag; Ps-staged
// coalesced stores; fused vscale. 4-stage cp.async with tail commits.
// ===========================================================================
#define SC_P 72
#define SC_QP 72
#define SC_PP 72
#define SC_STG_H (64*SC_P)
#define SC_SMEM (4*SC_STG_H*2)
#define ONES2 0x3C003C00u

__global__ void __launch_bounds__(256)
scores_h(const float* __restrict__ qmask, const float* __restrict__ kmask)
{
    extern __shared__ __half sh[];
    __shared__ __align__(16) __half Qs[64*SC_QP];   // [q][d], pre-scaled
    __shared__ __align__(16) __half Ps[64*SC_PP];   // staged P tile [q][k]
    __shared__ float lw[4][2][16];
    __shared__ float rls[64];
    __shared__ __half qsh[64];

    const int b = blockIdx.z, h = blockIdx.y, q0 = blockIdx.x * 64;
    const __half* Q = g_qp + ((size_t)b * EE + h * DHH) * TT;
    const __half* K = g_kp + ((size_t)b * EE + h * DHH) * TT;
    __half* P = g_att + (size_t)(b * HH + h) * TT * TT;

    const int tid = threadIdx.x, lane = tid & 31, warp = tid >> 5;
    const int g = lane >> 2, t4 = lane & 3;
    const int wm = warp >> 1, wn = warp & 1;
    const int l15 = lane & 15, lhi = (lane >> 4) * 8;
    const int wq = wm * 16;

    auto issueK = [&](int s) {
        int kc = s * 64;
        unsigned kb = smaddr(sh + (s & 3) * SC_STG_H);
        #pragma unroll
        for (int l = 0; l < 2; l++) {
            int idx = tid + l * 256;
            int d = idx >> 3, c8 = (idx & 7) * 8;
            cpa16(kb + (d * SC_P + c8) * 2, K + (size_t)d * TT + kc + c8);
        }
        cpa_commit();
    };

    issueK(0); issueK(1); issueK(2);

    if (tid < 64)
        qsh[tid] = __float2half_rn(qmask[(size_t)b * TT + q0 + tid] * S2LOG2E);
    __syncthreads();

    // stage Q tile transposed + pre-scaled: Qs[q][d] = Q[d][q]*qsh[q]
    #pragma unroll
    for (int l = 0; l < 8; l++) {
        int idx = tid + l * 256;
        int d = idx >> 5, q2 = (idx & 31) * 2;
        __half2 v = *(const __half2*)&Q[(size_t)d * TT + q0 + q2];
        __half2 r = __hmul2(v, __halves2half2(qsh[q2], qsh[q2 + 1]));
        Qs[(q2+0)*SC_QP + d] = __low2half(r);
        Qs[(q2+1)*SC_QP + d] = __high2half(r);
    }
    __syncthreads();

    // Q fragments resident for 4 ksteps, non-trans ldsm
    unsigned areg[4][4];
    const unsigned qsa = smaddr(Qs);
    #pragma unroll
    for (int ks = 0; ks < 4; ks++)
        ldsm4(areg[ks], qsa + ((wq + l15) * SC_QP + ks*16 + lhi) * 2);

    float lacc[4];
    lacc[0] = lacc[1] = lacc[2] = lacc[3] = 0.f;
    const unsigned onesb[2] = {ONES2, ONES2};

    const int NS = TT / 64;  // 32
    for (int s = 0; s < NS; s++) {
        cpa_wait<2>();
        __syncthreads();
        unsigned ksa = smaddr(sh + (s & 3) * SC_STG_H);

        float sc[4][4];
        #pragma unroll
        for (int nt = 0; nt < 4; nt++)
            #pragma unroll
            for (int e = 0; e < 4; e++) sc[nt][e] = 0.f;

        #pragma unroll
        for (int ks = 0; ks < 4; ks++) {
            unsigned bf[4][2];
            #pragma unroll
            for (int nb = 0; nb < 2; nb++) {
                unsigned r[4];
                ldsm4t(r, ksa + ((ks*16 + l15) * SC_P + wn*32 + nb*16 + lhi) * 2);
                bf[2*nb][0]   = r[0]; bf[2*nb][1]   = r[1];
                bf[2*nb+1][0] = r[2]; bf[2*nb+1][1] = r[3];
            }
            #pragma unroll
            for (int nt = 0; nt < 4; nt++)
                mma16(sc[nt], areg[ks], bf[nt]);
        }

        const int kc = s * 64;
        unsigned pe[4][2];   // post-exp half2 pairs: [nt][row01]
        #pragma unroll
        for (int nt = 0; nt < 4; nt++) {
            int kcol = wn * 32 + nt * 8 + 2 * t4;
            unsigned km2 = *(const unsigned*)&g_kmh[(size_t)b * TT + kc + kcol];
            unsigned a0 = h2u(__floats2half2_rn(sc[nt][0], sc[nt][1]));
            unsigned a1 = h2u(__floats2half2_rn(sc[nt][2], sc[nt][3]));
            unsigned e0 = ex2h2(mulh2(a0, km2));
            unsigned e1 = ex2h2(mulh2(a1, km2));
            pe[nt][0] = e0;
            pe[nt][1] = e1;
            *(unsigned*)&Ps[(wq + g) * SC_PP + kcol]     = mulh2(e0, km2);
            *(unsigned*)&Ps[(wq + g + 8) * SC_PP + kcol] = mulh2(e1, km2);
        }
        // l partials via tensor core: C-frag half2 packs == A-frag layout
        {
            unsigned a01[4] = {pe[0][0], pe[0][1], pe[1][0], pe[1][1]};
            unsigned a23[4] = {pe[2][0], pe[2][1], pe[3][0], pe[3][1]};
            mma16(lacc, a01, onesb);
            mma16(lacc, a23, onesb);
        }
        __syncthreads();

        // coalesced 16B copy out: 64 rows x 128B
        #pragma unroll
        for (int l = 0; l < 2; l++) {
            int idx = tid + l * 256;
            int r = idx >> 3, c8 = (idx & 7) * 8;
            *(uint4*)&P[(size_t)(q0 + r) * TT + kc + c8] =
                *(const uint4*)&Ps[r * SC_PP + c8];
        }

        if (s + 3 < NS) issueK(s + 3);
        else            cpa_commit();
    }

    // lacc[0] = l-partial row (wq+g), lacc[2] = row (wq+g+8); replicated
    if (t4 == 0) { lw[wm][wn][g] = lacc[0]; lw[wm][wn][g + 8] = lacc[2]; }
    __syncthreads();
    if (tid < 64) {
        float l = lw[tid >> 4][0][tid & 15] + lw[tid >> 4][1][tid & 15];
        rls[tid] = 1.0f / l;
    }
    __syncthreads();

    // fused vscale: V'[d, q0+q] = V[d, q0+q] * rl[q]
    {
        const __half* Vb = g_vp + ((size_t)b * EE + h * DHH) * TT + q0;
        __half*       Vo = g_vs + ((size_t)b * EE + h * DHH) * TT + q0;
        #pragma unroll
        for (int l = 0; l < 8; l++) {
            int idx = tid + l * 256;          // 2048 half2 over 64d x 64q
            int d = idx >> 5, q2 = (idx & 31) * 2;
            float2 v = __half22float2(*(const __half2*)&Vb[(size_t)d * TT + q2]);
            *(__half2*)&Vo[(size_t)d * TT + q2] =
                __floats2half2_rn(v.x * rls[q2], v.y * rls[q2 + 1]);
        }
    }
}

// ===========================================================================
// AV (round-11 proven): O[d,k] = sum_q V'[d,q] P[q,k]. 64(d)x128(k), q staged
// 32, 4-stage cp.async with tail commits. 8 warps = 2(m) x 4(n).
// ===========================================================================
#define AV_AP 40
#define AV_BP 136
#define AV_A_H (64*AV_AP)
#define AV_STG_H (AV_A_H + 32*AV_BP)
#define AV_SMEM (4*AV_STG_H*2)

__global__ void __launch_bounds__(256)
av_h()
{
    extern __shared__ __half sh[];
    const int b = blockIdx.z, h = blockIdx.y, k0 = blockIdx.x * 128;
    const __half* V = g_vs + ((size_t)b * EE + h * DHH) * TT;
    const __half* P = g_att + (size_t)(b * HH + h) * TT * TT;
    __half* O = g_oh + ((size_t)b * EE + h * DHH) * TT;

    const int tid = threadIdx.x, lane = tid & 31, warp = tid >> 5;
    const int g = lane >> 2, t4 = lane & 3;
    const int wm = warp >> 2, wn = warp & 3;
    const int l15 = lane & 15, lhi = (lane >> 4) * 8;

    float acc[2][4][4];
    #pragma unroll
    for (int i = 0; i < 2; i++)
        #pragma unroll
        for (int j = 0; j < 4; j++)
            #pragma unroll
            for (int e = 0; e < 4; e++) acc[i][j][e] = 0.f;

    auto issue = [&](int s) {
        int qc = s * 32;
        unsigned ab = smaddr(sh + (s & 3) * AV_STG_H);
        unsigned bb = ab + AV_A_H * 2;
        {
            int r = tid >> 2, c8 = (tid & 3) * 8;
            cpa16(ab + (r * AV_AP + c8) * 2, V + (size_t)r * TT + qc + c8);
        }
        #pragma unroll
        for (int l = 0; l < 2; l++) {
            int idx = tid + l * 256;
            int r = idx >> 4, c8 = (idx & 15) * 8;
            cpa16(bb + (r * AV_BP + c8) * 2, P + (size_t)(qc + r) * TT + k0 + c8);
        }
        cpa_commit();
    };

    const int NS = TT / 32;
    issue(0); issue(1); issue(2);

    for (int s = 0; s < NS; s++) {
        cpa_wait<2>();
        __syncthreads();
        unsigned ab = smaddr(sh + (s & 3) * AV_STG_H);
        unsigned bb = ab + AV_A_H * 2;
        #pragma unroll
        for (int ks = 0; ks < 2; ks++) {
            unsigned a[2][4], bf[4][2];
            #pragma unroll
            for (int mt = 0; mt < 2; mt++)
                ldsm4(a[mt], ab + ((wm*32 + mt*16 + l15) * AV_AP + ks*16 + lhi) * 2);
            #pragma unroll
            for (int nb = 0; nb < 2; nb++) {
                unsigned r[4];
                ldsm4t(r, bb + ((ks*16 + l15) * AV_BP + wn*32 + nb*16 + lhi) * 2);
                bf[2*nb][0]   = r[0]; bf[2*nb][1]   = r[1];
                bf[2*nb+1][0] = r[2]; bf[2*nb+1][1] = r[3];
            }
            #pragma unroll
            for (int mt = 0; mt < 2; mt++)
                #pragma unroll
                for (int nt = 0; nt < 4; nt++)
                    mma16(acc[mt][nt], a[mt], bf[nt]);
        }
        if (s + 3 < NS) issue(s + 3);
        else            cpa_commit();
    }

    #pragma unroll
    for (int mt = 0; mt < 2; mt++) {
        int d = wm * 32 + mt * 16 + g;
        #pragma unroll
        for (int nt = 0; nt < 4; nt++) {
            int kcol = k0 + wn * 32 + nt * 8 + 2 * t4;
            *(__half2*)&O[(size_t)d * TT + kcol] =
                __floats2half2_rn(acc[mt][nt][0], acc[mt][nt][1]);
            *(__half2*)&O[(size_t)(d + 8) * TT + kcol] =
                __floats2half2_rn(acc[mt][nt][2], acc[mt][nt][3]);
        }
    }
}

// ===========================================================================
extern "C" void kernel_launch(void* const* d_in, const int* in_sizes, int n_in,
                              void* d_out, int out_size)
{
    const float* q   = (const float*)d_in[0];
    const float* k   = (const float*)d_in[1];
    const float* v   = (const float*)d_in[2];
    const float* qm  = (const float*)d_in[3];
    const float* km  = (const float*)d_in[4];
    const float* vm  = (const float*)d_in[5];
    const float* Wq  = (const float*)d_in[6];
    const float* bq  = (const float*)d_in[7];
    const float* Wk  = (const float*)d_in[8];
    const float* bk  = (const float*)d_in[9];
    const float* Wv  = (const float*)d_in[10];
    const float* bv  = (const float*)d_in[11];
    const float* Wo  = (const float*)d_in[12];
    const float* bo  = (const float*)d_in[13];
    float* out = (float*)d_out;

    cudaFuncSetAttribute(conv3_kernel,      cudaFuncAttributeMaxDynamicSharedMemorySize, CV_SMEM);
    cudaFuncSetAttribute(conv_final_kernel, cudaFuncAttributeMaxDynamicSharedMemorySize, CV_SMEM);
    cudaFuncSetAttribute(scores_h,          cudaFuncAttributeMaxDynamicSharedMemorySize, SC_SMEM);
    cudaFuncSetAttribute(av_h,              cudaFuncAttributeMaxDynamicSharedMemorySize, AV_SMEM);

    cvt_in<<<dim3(BB*EE*TT/1024, 1, 3), 256>>>(q, k, v);
    cvt_w <<<dim3(EE*EE/1024,    1, 4), 256>>>(Wq, Wk, Wv, Wo);
    cvt_km<<<BB*TT/256, 256>>>(km);

    dim3 g1(TT / 128, EE / 128, 3 * BB);
    conv3_kernel<<<g1, 256, CV_SMEM>>>(qm, km, vm, bq, bk, bv);

    dim3 g2(TT / 64, HH, BB);
    scores_h<<<g2, 256, SC_SMEM>>>(qm, km);

    dim3 g3(TT / 128, HH, BB);
    av_h<<<g3, 256, AV_SMEM>>>();

    dim3 g4(TT / 128, EE / 128, BB);
    conv_final_kernel<<<g4, 256, CV_SMEM>>>(bo, km, out);
}

// round 17
// speedup vs baseline: 1.1534x; 1.1534x over previous
#include <cuda_runtime.h>
#include <cuda_fp16.h>

#define BB 2
#define EE 1024
#define TT 2048
#define HH 16
#define DHH 64
#define SCALE 0.03125f
#define S2LOG2E 0.045084235f   // SCALE * log2(e)

// ---------------------------------------------------------------------------
// fp16 scratch (static device arrays; 16B aligned for cp.async / vector ops)
// ---------------------------------------------------------------------------
__device__ __align__(16) __half g_xh[3*BB*EE*TT];   // converted q,k,v inputs
__device__ __align__(16) __half g_wh[4*EE*EE];      // converted Wq,Wk,Wv,Wo
__device__ __align__(16) __half g_qp[BB*EE*TT];     // Q proj [e][t]
__device__ __align__(16) __half g_kp[BB*EE*TT];     // K proj [e][t]
__device__ __align__(16) __half g_vp[BB*EE*TT];     // V proj [e][t]
__device__ __align__(16) __half g_vs[BB*EE*TT];     // V * rl
__device__ __align__(16) __half g_oh[BB*EE*TT];     // attention output O
__device__ __align__(16) __half g_att[(size_t)BB*HH*TT*TT];  // unnorm exp(s)*km
__device__ __align__(16) __half g_kmh[BB*TT];       // fp16 key mask

// ---------------------------------------------------------------------------
__device__ __forceinline__ unsigned smaddr(const void* p){
    return (unsigned)__cvta_generic_to_shared(p);
}
__device__ __forceinline__ void cpa16(unsigned dst, const void* src){
    asm volatile("cp.async.cg.shared.global [%0], [%1], 16;" :: "r"(dst), "l"(src));
}
__device__ __forceinline__ void cpa_commit(){
    asm volatile("cp.async.commit_group;");
}
template<int N> __device__ __forceinline__ void cpa_wait(){
    asm volatile("cp.async.wait_group %0;" :: "n"(N));
}
__device__ __forceinline__ void ldsm4(unsigned r[4], unsigned addr){
    asm volatile("ldmatrix.sync.aligned.m8n8.x4.shared.b16 {%0,%1,%2,%3}, [%4];"
        : "=r"(r[0]),"=r"(r[1]),"=r"(r[2]),"=r"(r[3]) : "r"(addr));
}
__device__ __forceinline__ void ldsm4t(unsigned r[4], unsigned addr){
    asm volatile("ldmatrix.sync.aligned.m8n8.x4.trans.shared.b16 {%0,%1,%2,%3}, [%4];"
        : "=r"(r[0]),"=r"(r[1]),"=r"(r[2]),"=r"(r[3]) : "r"(addr));
}
__device__ __forceinline__ void mma16(float c[4], const unsigned a[4], const unsigned b[2]){
    asm volatile("mma.sync.aligned.m16n8k16.row.col.f32.f16.f16.f32 "
        "{%0,%1,%2,%3},{%4,%5,%6,%7},{%8,%9},{%0,%1,%2,%3};"
        : "+f"(c[0]),"+f"(c[1]),"+f"(c[2]),"+f"(c[3])
        : "r"(a[0]),"r"(a[1]),"r"(a[2]),"r"(a[3]),"r"(b[0]),"r"(b[1]));
}
__device__ __forceinline__ unsigned h2u(__half2 h){
    return *reinterpret_cast<unsigned*>(&h);
}
__device__ __forceinline__ unsigned ex2h2(unsigned x){
    unsigned r;
    asm("ex2.approx.f16x2 %0, %1;" : "=r"(r) : "r"(x));
    return r;
}
__device__ __forceinline__ unsigned mulh2(unsigned a, unsigned b){
    unsigned r;
    asm("mul.f16x2 %0, %1, %2;" : "=r"(r) : "r"(a), "r"(b));
    return r;
}

// ===========================================================================
// Converters
// ===========================================================================
__global__ void __launch_bounds__(256)
cvt_in(const float* __restrict__ q, const float* __restrict__ k,
       const float* __restrict__ v)
{
    const float* src = (blockIdx.z == 0) ? q : (blockIdx.z == 1) ? k : v;
    __half* dst = g_xh + (size_t)blockIdx.z * BB * EE * TT;
    size_t i = ((size_t)blockIdx.x * 256 + threadIdx.x) * 4;
    float4 x = *(const float4*)&src[i];
    *(__half2*)&dst[i]     = __floats2half2_rn(x.x, x.y);
    *(__half2*)&dst[i + 2] = __floats2half2_rn(x.z, x.w);
}

__global__ void __launch_bounds__(256)
cvt_w(const float* __restrict__ wq, const float* __restrict__ wk,
      const float* __restrict__ wv, const float* __restrict__ wo)
{
    const float* src = (blockIdx.z == 0) ? wq : (blockIdx.z == 1) ? wk :
                       (blockIdx.z == 2) ? wv : wo;
    __half* dst = g_wh + (size_t)blockIdx.z * EE * EE;
    size_t i = ((size_t)blockIdx.x * 256 + threadIdx.x) * 4;
    float4 x = *(const float4*)&src[i];
    *(__half2*)&dst[i]     = __floats2half2_rn(x.x, x.y);
    *(__half2*)&dst[i + 2] = __floats2half2_rn(x.z, x.w);
}

__global__ void __launch_bounds__(256)
cvt_km(const float* __restrict__ km)
{
    int i = blockIdx.x * 256 + threadIdx.x;   // BB*TT = 4096
    g_kmh[i] = __float2half_rn(km[i]);
}

// ===========================================================================
// conv1x1 GEMM (fp16 in, fp32 acc): Y[o,t] = mask[t]*sum_c W[o,c]X[c,t] + b[o]
// 128(o)x128(t) tile, 256 thr (round-14 proven inner shape), BK=64:
// 16 K-stages (half the barriers), 3-stage ring (2-in-flight = 70 KB depth),
// 105 KB smem -> 2 CTA/SM (regs bind there anyway). Tail commits.
// ===========================================================================
#define CV_AP 72
#define CV_BP 136
#define CV_A_H  (128*CV_AP)                 // 9216 halves
#define CV_STG_H (CV_A_H + 64*CV_BP)        // 17920 halves
#define CV_SMEM (3*CV_STG_H*2)              // 107520 B

template<bool OUT_HALF>
__device__ __forceinline__ void gemm_conv(
    const __half* __restrict__ Wh, const __half* __restrict__ Xb,
    const float* __restrict__ bias, const float* __restrict__ maskb,
    void* __restrict__ Yv, size_t y_off)
{
    extern __shared__ __half sh[];
    const int tid = threadIdx.x, lane = tid & 31, warp = tid >> 5;
    const int g = lane >> 2, t4 = lane & 3;
    const int wm = warp >> 1, wn = warp & 1;
    const int l15 = lane & 15, lhi = (lane >> 4) * 8;
    const int o0 = blockIdx.y * 128, t0 = blockIdx.x * 128;

    float acc[2][8][4];
    #pragma unroll
    for (int i = 0; i < 2; i++)
        #pragma unroll
        for (int j = 0; j < 8; j++)
            #pragma unroll
            for (int e = 0; e < 4; e++) acc[i][j][e] = 0.f;

    auto issue = [&](int s) {
        int k0 = s * 64;
        unsigned ab = smaddr(sh + (s % 3) * CV_STG_H);
        unsigned bb = ab + CV_A_H * 2;
        #pragma unroll
        for (int l = 0; l < 4; l++) {
            int idx = tid + l * 256;               // 1024 chunks over W 128x64
            int r = idx >> 3, c8 = (idx & 7) * 8;
            cpa16(ab + (r * CV_AP + c8) * 2, Wh + (size_t)(o0 + r) * EE + k0 + c8);
        }
        #pragma unroll
        for (int l = 0; l < 4; l++) {
            int idx = tid + l * 256;               // 1024 chunks over X 64x128
            int r = idx >> 4, c8 = (idx & 15) * 8;
            cpa16(bb + (r * CV_BP + c8) * 2, Xb + (size_t)(k0 + r) * TT + t0 + c8);
        }
        cpa_commit();
    };

    const int NS = EE / 64;   // 16
    issue(0); issue(1);

    for (int s = 0; s < NS; s++) {
        cpa_wait<1>();
        __syncthreads();
        unsigned ab = smaddr(sh + (s % 3) * CV_STG_H);
        unsigned bb = ab + CV_A_H * 2;
        #pragma unroll
        for (int kk = 0; kk < 64; kk += 16) {
            unsigned a[2][4], bf[8][2];
            #pragma unroll
            for (int mt = 0; mt < 2; mt++)
                ldsm4(a[mt], ab + ((wm*32 + mt*16 + l15) * CV_AP + kk + lhi) * 2);
            #pragma unroll
            for (int nb = 0; nb < 4; nb++) {
                unsigned r[4];
                ldsm4t(r, bb + ((kk + l15) * CV_BP + wn*64 + nb*16 + lhi) * 2);
                bf[2*nb][0]   = r[0]; bf[2*nb][1]   = r[1];
                bf[2*nb+1][0] = r[2]; bf[2*nb+1][1] = r[3];
            }
            #pragma unroll
            for (int mt = 0; mt < 2; mt++)
                #pragma unroll
                for (int nt = 0; nt < 8; nt++)
                    mma16(acc[mt][nt], a[mt], bf[nt]);
        }
        if (s + 2 < NS) issue(s + 2);
        else            cpa_commit();   // tail: committed stays s+3
    }

    #pragma unroll
    for (int mt = 0; mt < 2; mt++) {
        int o_lo = o0 + wm * 32 + mt * 16 + g;
        float b_lo = bias[o_lo], b_hi = bias[o_lo + 8];
        #pragma unroll
        for (int nt = 0; nt < 8; nt++) {
            int t = t0 + wn * 64 + nt * 8 + 2 * t4;
            float mk0 = maskb[t], mk1 = maskb[t + 1];
            float y00 = mk0 * acc[mt][nt][0] + b_lo;
            float y01 = mk1 * acc[mt][nt][1] + b_lo;
            float y10 = mk0 * acc[mt][nt][2] + b_hi;
            float y11 = mk1 * acc[mt][nt][3] + b_hi;
            if (OUT_HALF) {
                __half* Y = (__half*)Yv + y_off;
                *(__half2*)&Y[(size_t)o_lo * TT + t]       = __floats2half2_rn(y00, y01);
                *(__half2*)&Y[(size_t)(o_lo + 8) * TT + t] = __floats2half2_rn(y10, y11);
            } else {
                float* Y = (float*)Yv + y_off;
                *(float2*)&Y[(size_t)o_lo * TT + t]       = make_float2(y00, y01);
                *(float2*)&Y[(size_t)(o_lo + 8) * TT + t] = make_float2(y10, y11);
            }
        }
    }
}

__global__ void __launch_bounds__(256)
conv3_kernel(const float* __restrict__ qm, const float* __restrict__ km,
             const float* __restrict__ vm,
             const float* __restrict__ bq, const float* __restrict__ bk,
             const float* __restrict__ bv)
{
    int m = blockIdx.z >> 1;
    int b = blockIdx.z & 1;
    const __half* Wh = g_wh + (size_t)m * EE * EE;
    const __half* Xb = g_xh + ((size_t)m * BB + b) * EE * TT;
    size_t yoff = (size_t)b * EE * TT;
    const float* mask = ((m == 0) ? qm : (m == 1) ? km : vm) + (size_t)b * TT;
    const float* bias = (m == 0) ? bq : (m == 1) ? bk : bv;
    __half* Y = (m == 0) ? g_qp : (m == 1) ? g_kp : g_vp;
    gemm_conv<true>(Wh, Xb, bias, mask, Y, yoff);
}

__global__ void __launch_bounds__(256)
conv_final_kernel(const float* __restrict__ bo, const float* __restrict__ km,
                  float* __restrict__ out)
{
    int b = blockIdx.z;
    gemm_conv<false>(g_wh + (size_t)3 * EE * EE,
                     g_oh + (size_t)b * EE * TT,
                     bo, km + (size_t)b * TT, out, (size_t)b * EE * TT);
}

// ===========================================================================
// Scores (round-14 proven, ~108us): per (b,h, 64 q rows).
// P[q,k] = exp(s*qm*km*scale)*km (fp16). Q pre-scaled at staging; fp16 kmask;
// half2 epilogue via ex2.approx.f16x2; l via mma vs ones B-frag; Ps-staged
// coalesced stores; fused vscale. 4-stage cp.async with tail commits.
// ===========================================================================
#define SC_P 72
#define SC_QP 72
#define SC_PP 72
#define SC_STG_H (64*SC_P)
#define SC_SMEM (4*SC_STG_H*2)
#define ONES2 0x3C003C00u

__global__ void __launch_bounds__(256)
scores_h(const float* __restrict__ qmask, const float* __restrict__ kmask)
{
    extern __shared__ __half sh[];
    __shared__ __align__(16) __half Qs[64*SC_QP];   // [q][d], pre-scaled
    __shared__ __align__(16) __half Ps[64*SC_PP];   // staged P tile [q][k]
    __shared__ float lw[4][2][16];
    __shared__ float rls[64];
    __shared__ __half qsh[64];

    const int b = blockIdx.z, h = blockIdx.y, q0 = blockIdx.x * 64;
    const __half* Q = g_qp + ((size_t)b * EE + h * DHH) * TT;
    const __half* K = g_kp + ((size_t)b * EE + h * DHH) * TT;
    __half* P = g_att + (size_t)(b * HH + h) * TT * TT;

    const int tid = threadIdx.x, lane = tid & 31, warp = tid >> 5;
    const int g = lane >> 2, t4 = lane & 3;
    const int wm = warp >> 1, wn = warp & 1;
    const int l15 = lane & 15, lhi = (lane >> 4) * 8;
    const int wq = wm * 16;

    auto issueK = [&](int s) {
        int kc = s * 64;
        unsigned kb = smaddr(sh + (s & 3) * SC_STG_H);
        #pragma unroll
        for (int l = 0; l < 2; l++) {
            int idx = tid + l * 256;
            int d = idx >> 3, c8 = (idx & 7) * 8;
            cpa16(kb + (d * SC_P + c8) * 2, K + (size_t)d * TT + kc + c8);
        }
        cpa_commit();
    };

    issueK(0); issueK(1); issueK(2);

    if (tid < 64)
        qsh[tid] = __float2half_rn(qmask[(size_t)b * TT + q0 + tid] * S2LOG2E);
    __syncthreads();

    // stage Q tile transposed + pre-scaled: Qs[q][d] = Q[d][q]*qsh[q]
    #pragma unroll
    for (int l = 0; l < 8; l++) {
        int idx = tid + l * 256;
        int d = idx >> 5, q2 = (idx & 31) * 2;
        __half2 v = *(const __half2*)&Q[(size_t)d * TT + q0 + q2];
        __half2 r = __hmul2(v, __halves2half2(qsh[q2], qsh[q2 + 1]));
        Qs[(q2+0)*SC_QP + d] = __low2half(r);
        Qs[(q2+1)*SC_QP + d] = __high2half(r);
    }
    __syncthreads();

    // Q fragments resident for 4 ksteps, non-trans ldsm
    unsigned areg[4][4];
    const unsigned qsa = smaddr(Qs);
    #pragma unroll
    for (int ks = 0; ks < 4; ks++)
        ldsm4(areg[ks], qsa + ((wq + l15) * SC_QP + ks*16 + lhi) * 2);

    float lacc[4];
    lacc[0] = lacc[1] = lacc[2] = lacc[3] = 0.f;
    const unsigned onesb[2] = {ONES2, ONES2};

    const int NS = TT / 64;  // 32
    for (int s = 0; s < NS; s++) {
        cpa_wait<2>();
        __syncthreads();
        unsigned ksa = smaddr(sh + (s & 3) * SC_STG_H);

        float sc[4][4];
        #pragma unroll
        for (int nt = 0; nt < 4; nt++)
            #pragma unroll
            for (int e = 0; e < 4; e++) sc[nt][e] = 0.f;

        #pragma unroll
        for (int ks = 0; ks < 4; ks++) {
            unsigned bf[4][2];
            #pragma unroll
            for (int nb = 0; nb < 2; nb++) {
                unsigned r[4];
                ldsm4t(r, ksa + ((ks*16 + l15) * SC_P + wn*32 + nb*16 + lhi) * 2);
                bf[2*nb][0]   = r[0]; bf[2*nb][1]   = r[1];
                bf[2*nb+1][0] = r[2]; bf[2*nb+1][1] = r[3];
            }
            #pragma unroll
            for (int nt = 0; nt < 4; nt++)
                mma16(sc[nt], areg[ks], bf[nt]);
        }

        const int kc = s * 64;
        unsigned pe[4][2];   // post-exp half2 pairs: [nt][row01]
        #pragma unroll
        for (int nt = 0; nt < 4; nt++) {
            int kcol = wn * 32 + nt * 8 + 2 * t4;
            unsigned km2 = *(const unsigned*)&g_kmh[(size_t)b * TT + kc + kcol];
            unsigned a0 = h2u(__floats2half2_rn(sc[nt][0], sc[nt][1]));
            unsigned a1 = h2u(__floats2half2_rn(sc[nt][2], sc[nt][3]));
            unsigned e0 = ex2h2(mulh2(a0, km2));
            unsigned e1 = ex2h2(mulh2(a1, km2));
            pe[nt][0] = e0;
            pe[nt][1] = e1;
            *(unsigned*)&Ps[(wq + g) * SC_PP + kcol]     = mulh2(e0, km2);
            *(unsigned*)&Ps[(wq + g + 8) * SC_PP + kcol] = mulh2(e1, km2);
        }
        // l partials via tensor core: C-frag half2 packs == A-frag layout
        {
            unsigned a01[4] = {pe[0][0], pe[0][1], pe[1][0], pe[1][1]};
            unsigned a23[4] = {pe[2][0], pe[2][1], pe[3][0], pe[3][1]};
            mma16(lacc, a01, onesb);
            mma16(lacc, a23, onesb);
        }
        __syncthreads();

        // coalesced 16B copy out: 64 rows x 128B
        #pragma unroll
        for (int l = 0; l < 2; l++) {
            int idx = tid + l * 256;
            int r = idx >> 3, c8 = (idx & 7) * 8;
            *(uint4*)&P[(size_t)(q0 + r) * TT + kc + c8] =
                *(const uint4*)&Ps[r * SC_PP + c8];
        }

        if (s + 3 < NS) issueK(s + 3);
        else            cpa_commit();
    }

    // lacc[0] = l-partial row (wq+g), lacc[2] = row (wq+g+8); replicated
    if (t4 == 0) { lw[wm][wn][g] = lacc[0]; lw[wm][wn][g + 8] = lacc[2]; }
    __syncthreads();
    if (tid < 64) {
        float l = lw[tid >> 4][0][tid & 15] + lw[tid >> 4][1][tid & 15];
        rls[tid] = 1.0f / l;
    }
    __syncthreads();

    // fused vscale: V'[d, q0+q] = V[d, q0+q] * rl[q]
    {
        const __half* Vb = g_vp + ((size_t)b * EE + h * DHH) * TT + q0;
        __half*       Vo = g_vs + ((size_t)b * EE + h * DHH) * TT + q0;
        #pragma unroll
        for (int l = 0; l < 8; l++) {
            int idx = tid + l * 256;          // 2048 half2 over 64d x 64q
            int d = idx >> 5, q2 = (idx & 31) * 2;
            float2 v = __half22float2(*(const __half2*)&Vb[(size_t)d * TT + q2]);
            *(__half2*)&Vo[(size_t)d * TT + q2] =
                __floats2half2_rn(v.x * rls[q2], v.y * rls[q2 + 1]);
        }
    }
}

// ===========================================================================
// AV (round-11 proven): O[d,k] = sum_q V'[d,q] P[q,k]. 64(d)x128(k), q staged
// 32, 4-stage cp.async with tail commits. 8 warps = 2(m) x 4(n).
// ===========================================================================
#define AV_AP 40
#define AV_BP 136
#define AV_A_H (64*AV_AP)
#define AV_STG_H (AV_A_H + 32*AV_BP)
#define AV_SMEM (4*AV_STG_H*2)

__global__ void __launch_bounds__(256)
av_h()
{
    extern __shared__ __half sh[];
    const int b = blockIdx.z, h = blockIdx.y, k0 = blockIdx.x * 128;
    const __half* V = g_vs + ((size_t)b * EE + h * DHH) * TT;
    const __half* P = g_att + (size_t)(b * HH + h) * TT * TT;
    __half* O = g_oh + ((size_t)b * EE + h * DHH) * TT;

    const int tid = threadIdx.x, lane = tid & 31, warp = tid >> 5;
    const int g = lane >> 2, t4 = lane & 3;
    const int wm = warp >> 2, wn = warp & 3;
    const int l15 = lane & 15, lhi = (lane >> 4) * 8;

    float acc[2][4][4];
    #pragma unroll
    for (int i = 0; i < 2; i++)
        #pragma unroll
        for (int j = 0; j < 4; j++)
            #pragma unroll
            for (int e = 0; e < 4; e++) acc[i][j][e] = 0.f;

    auto issue = [&](int s) {
        int qc = s * 32;
        unsigned ab = smaddr(sh + (s & 3) * AV_STG_H);
        unsigned bb = ab + AV_A_H * 2;
        {
            int r = tid >> 2, c8 = (tid & 3) * 8;
            cpa16(ab + (r * AV_AP + c8) * 2, V + (size_t)r * TT + qc + c8);
        }
        #pragma unroll
        for (int l = 0; l < 2; l++) {
            int idx = tid + l * 256;
            int r = idx >> 4, c8 = (idx & 15) * 8;
            cpa16(bb + (r * AV_BP + c8) * 2, P + (size_t)(qc + r) * TT + k0 + c8);
        }
        cpa_commit();
    };

    const int NS = TT / 32;
    issue(0); issue(1); issue(2);

    for (int s = 0; s < NS; s++) {
        cpa_wait<2>();
        __syncthreads();
        unsigned ab = smaddr(sh + (s & 3) * AV_STG_H);
        unsigned bb = ab + AV_A_H * 2;
        #pragma unroll
        for (int ks = 0; ks < 2; ks++) {
            unsigned a[2][4], bf[4][2];
            #pragma unroll
            for (int mt = 0; mt < 2; mt++)
                ldsm4(a[mt], ab + ((wm*32 + mt*16 + l15) * AV_AP + ks*16 + lhi) * 2);
            #pragma unroll
            for (int nb = 0; nb < 2; nb++) {
                unsigned r[4];
                ldsm4t(r, bb + ((ks*16 + l15) * AV_BP + wn*32 + nb*16 + lhi) * 2);
                bf[2*nb][0]   = r[0]; bf[2*nb][1]   = r[1];
                bf[2*nb+1][0] = r[2]; bf[2*nb+1][1] = r[3];
            }
            #pragma unroll
            for (int mt = 0; mt < 2; mt++)
                #pragma unroll
                for (int nt = 0; nt < 4; nt++)
                    mma16(acc[mt][nt], a[mt], bf[nt]);
        }
        if (s + 3 < NS) issue(s + 3);
        else            cpa_commit();
    }

    #pragma unroll
    for (int mt = 0; mt < 2; mt++) {
        int d = wm * 32 + mt * 16 + g;
        #pragma unroll
        for (int nt = 0; nt < 4; nt++) {
            int kcol = k0 + wn * 32 + nt * 8 + 2 * t4;
            *(__half2*)&O[(size_t)d * TT + kcol] =
                __floats2half2_rn(acc[mt][nt][0], acc[mt][nt][1]);
            *(__half2*)&O[(size_t)(d + 8) * TT + kcol] =
                __floats2half2_rn(acc[mt][nt][2], acc[mt][nt][3]);
        }
    }
}

// ===========================================================================
extern "C" void kernel_launch(void* const* d_in, const int* in_sizes, int n_in,
                              void* d_out, int out_size)
{
    const float* q   = (const float*)d_in[0];
    const float* k   = (const float*)d_in[1];
    const float* v   = (const float*)d_in[2];
    const float* qm  = (const float*)d_in[3];
    const float* km  = (const float*)d_in[4];
    const float* vm  = (const float*)d_in[5];
    const float* Wq  = (const float*)d_in[6];
    const float* bq  = (const float*)d_in[7];
    const float* Wk  = (const float*)d_in[8];
    const float* bk  = (const float*)d_in[9];
    const float* Wv  = (const float*)d_in[10];
    const float* bv  = (const float*)d_in[11];
    const float* Wo  = (const float*)d_in[12];
    const float* bo  = (const float*)d_in[13];
    float* out = (float*)d_out;

    cudaFuncSetAttribute(conv3_kernel,      cudaFuncAttributeMaxDynamicSharedMemorySize, CV_SMEM);
    cudaFuncSetAttribute(conv_final_kernel, cudaFuncAttributeMaxDynamicSharedMemorySize, CV_SMEM);
    cudaFuncSetAttribute(scores_h,          cudaFuncAttributeMaxDynamicSharedMemorySize, SC_SMEM);
    cudaFuncSetAttribute(av_h,              cudaFuncAttributeMaxDynamicSharedMemorySize, AV_SMEM);

    cvt_in<<<dim3(BB*EE*TT/1024, 1, 3), 256>>>(q, k, v);
    cvt_w <<<dim3(EE*EE/1024,    1, 4), 256>>>(Wq, Wk, Wv, Wo);
    cvt_km<<<BB*TT/256, 256>>>(km);

    dim3 g1(TT / 128, EE / 128, 3 * BB);
    conv3_kernel<<<g1, 256, CV_SMEM>>>(qm, km, vm, bq, bk, bv);

    dim3 g2(TT / 64, HH, BB);
    scores_h<<<g2, 256, SC_SMEM>>>(qm, km);

    dim3 g3(TT / 128, HH, BB);
    av_h<<<g3, 256, AV_SMEM>>>();

    dim3 g4(TT / 128, EE / 128, BB);
    conv_final_kernel<<<g4, 256, CV_SMEM>>>(bo, km, out);
}